// round 6
// baseline (speedup 1.0000x reference)
#include <cuda_runtime.h>
#include <cuda_fp16.h>

#define D      128
#define NMAX   100000
#define NP     (NMAX + 1)
#define EMAX   1600000
#define SCAN_B 1024
#define NBLK   ((NP + SCAN_B - 1) / SCAN_B)   // 98

#define GEMM_BLOCKS ((NMAX + 127) / 128)      // 782 (128-row tiles)
#define CNT_BLOCKS  392

// Scratch (device globals — no allocations allowed)
__device__ __half g_X0h[(size_t)NMAX * D];    // notes @ w in fp16 (25.6 MB)
__device__ uint4  g_wfrag[8 * 16 * 32];       // B fragments: {bh0,bh1,bl0,bl1}
__device__ int    g_deg[NP];
__device__ int    g_offs[NP];
__device__ int    g_blk_flag[NBLK];           // 0 none, 1 aggregate, 2 inclusive
__device__ int    g_blk_agg[NBLK];
__device__ int    g_blk_inc[NBLK];
__device__ int2   g_csr[EMAX];                // packed {dst, w_bits}

static __device__ __forceinline__ unsigned pack_bf16x2(float f0, float f1) {
    unsigned h;
    asm("cvt.rn.bf16x2.f32 %0, %1, %2;" : "=r"(h) : "f"(f1), "f"(f0));
    return h;
}

static __device__ __forceinline__ void cp_async16(void* sdst, const void* gsrc,
                                                  int src_bytes) {
    unsigned sa = (unsigned)__cvta_generic_to_shared(sdst);
    asm volatile("cp.async.cg.shared.global [%0], [%1], 16, %2;\n"
                 :: "r"(sa), "l"(gsrc), "r"(src_bytes));
}

// ---------------------------------------------------------------------------
// Prep: blocks [0,16) build w fragments in mma register order;
//       blocks [16,..) zero g_deg and scan state.
// ---------------------------------------------------------------------------
__global__ void prep_kernel(const float* __restrict__ w) {
    if (blockIdx.x < 16) {
        int f = blockIdx.x * 256 + threadIdx.x;   // 0..4095
        int lane = f & 31;
        int nt   = (f >> 5) & 15;
        int ks   = f >> 9;
        int g  = lane >> 2;
        int tq = lane & 3;
        int n  = nt * 8 + g;
        int k0 = ks * 16 + 2 * tq;
        int k1 = k0 + 8;

        float a0 = w[(k0)     * D + n];
        float a1 = w[(k0 + 1) * D + n];
        float c0 = w[(k1)     * D + n];
        float c1 = w[(k1 + 1) * D + n];

        unsigned bh0 = pack_bf16x2(a0, a1);
        unsigned bh1 = pack_bf16x2(c0, c1);
        float h0 = __uint_as_float(bh0 << 16);
        float h1 = __uint_as_float(bh0 & 0xffff0000u);
        float h2 = __uint_as_float(bh1 << 16);
        float h3 = __uint_as_float(bh1 & 0xffff0000u);
        unsigned bl0 = pack_bf16x2(a0 - h0, a1 - h1);
        unsigned bl1 = pack_bf16x2(c0 - h2, c1 - h3);

        g_wfrag[f] = make_uint4(bh0, bh1, bl0, bl1);
    } else {
        int z = (blockIdx.x - 16) * 256 + threadIdx.x;
        if (z < NP) g_deg[z] = 0;
        if (z < NBLK) { g_blk_flag[z] = 0; g_blk_agg[z] = 0; g_blk_inc[z] = 0; }
    }
}

// ---------------------------------------------------------------------------
// Fused tensor-core GEMM + degree count.
// GEMM blocks: 128 rows x 128 cols, 256 threads (8 warps), cp.async staging.
// Count blocks (tail): int4 grid-stride degree histogram.
// ---------------------------------------------------------------------------
#define SN_PITCH 132

__global__ void __launch_bounds__(256) gemm_count_kernel(
        const float* __restrict__ notes,
        const int*   __restrict__ esrc,
        float* __restrict__ out, int N, int garment, int E) {
    if (blockIdx.x >= GEMM_BLOCKS) {
        // ---- degree count path ----
        int cb   = blockIdx.x - GEMM_BLOCKS;
        int tidg = cb * 256 + threadIdx.x;
        int nth  = CNT_BLOCKS * 256;
        int E4   = E >> 2;
        const int4* s4 = (const int4*)esrc;
        for (int i = tidg; i < E4; i += nth) {
            int4 s = s4[i];
            atomicAdd(&g_deg[s.x], 1);
            atomicAdd(&g_deg[s.y], 1);
            atomicAdd(&g_deg[s.z], 1);
            atomicAdd(&g_deg[s.w], 1);
        }
        if (tidg == 0)
            for (int e = E4 << 2; e < E; e++) atomicAdd(&g_deg[esrc[e]], 1);
        return;
    }

    extern __shared__ char smem_raw[];
    uint4* s_bf = (uint4*)smem_raw;                           // 4096 uint4 (64KB)
    float* s_n  = (float*)(smem_raw + 4096 * 16);             // [128][132] f32

    const int t    = threadIdx.x;
    const int warp = t >> 5;
    const int lane = t & 31;
    const int g    = lane >> 2;
    const int tq   = lane & 3;
    const int row0 = blockIdx.x * 128;

    // Stage B fragments (4096 uint4) via cp.async
    #pragma unroll
    for (int i = t; i < 4096; i += 256)
        cp_async16(&s_bf[i], &g_wfrag[i], 16);

    // Stage notes tile (128 x 128 f32 = 4096 float4), zero-fill OOB rows
    const float4* n4 = (const float4*)notes;
    #pragma unroll
    for (int i = t; i < 4096; i += 256) {
        int r = i >> 5, c4 = i & 31;
        int gr = row0 + r;
        const float4* src = (gr < N) ? (n4 + (size_t)gr * 32 + c4) : n4;
        cp_async16(&s_n[r * SN_PITCH + c4 * 4], src, (gr < N) ? 16 : 0);
    }
    asm volatile("cp.async.commit_group;\n");
    asm volatile("cp.async.wait_all;\n" ::: "memory");
    __syncthreads();

    float acc[16][4];
    #pragma unroll
    for (int nt = 0; nt < 16; nt++)
        #pragma unroll
        for (int j = 0; j < 4; j++) acc[nt][j] = 0.f;

    const int arow = warp * 16 + g;

    #pragma unroll
    for (int ks = 0; ks < 8; ks++) {
        // A fragments: f32 -> bf16 hi/lo split on the fly
        unsigned ahi[4], alo[4];
        #pragma unroll
        for (int i = 0; i < 4; i++) {
            int r = arow + (i & 1) * 8;
            int k = ks * 16 + tq * 2 + (i >> 1) * 8;
            float2 f = *(const float2*)&s_n[r * SN_PITCH + k];
            unsigned h = pack_bf16x2(f.x, f.y);
            float hx = __uint_as_float(h << 16);
            float hy = __uint_as_float(h & 0xffff0000u);
            ahi[i] = h;
            alo[i] = pack_bf16x2(f.x - hx, f.y - hy);
        }
        const uint4* bf = &s_bf[ks * 16 * 32 + lane];
        #pragma unroll
        for (int nt = 0; nt < 16; nt++) {
            uint4 f = bf[nt * 32];
            asm volatile(
                "mma.sync.aligned.m16n8k16.row.col.f32.bf16.bf16.f32 "
                "{%0,%1,%2,%3}, {%4,%5,%6,%7}, {%8,%9}, {%0,%1,%2,%3};"
                : "+f"(acc[nt][0]), "+f"(acc[nt][1]), "+f"(acc[nt][2]), "+f"(acc[nt][3])
                : "r"(ahi[0]), "r"(ahi[1]), "r"(ahi[2]), "r"(ahi[3]),
                  "r"(f.x), "r"(f.y));
            asm volatile(
                "mma.sync.aligned.m16n8k16.row.col.f32.bf16.bf16.f32 "
                "{%0,%1,%2,%3}, {%4,%5,%6,%7}, {%8,%9}, {%0,%1,%2,%3};"
                : "+f"(acc[nt][0]), "+f"(acc[nt][1]), "+f"(acc[nt][2]), "+f"(acc[nt][3])
                : "r"(ahi[0]), "r"(ahi[1]), "r"(ahi[2]), "r"(ahi[3]),
                  "r"(f.z), "r"(f.w));
            asm volatile(
                "mma.sync.aligned.m16n8k16.row.col.f32.bf16.bf16.f32 "
                "{%0,%1,%2,%3}, {%4,%5,%6,%7}, {%8,%9}, {%0,%1,%2,%3};"
                : "+f"(acc[nt][0]), "+f"(acc[nt][1]), "+f"(acc[nt][2]), "+f"(acc[nt][3])
                : "r"(alo[0]), "r"(alo[1]), "r"(alo[2]), "r"(alo[3]),
                  "r"(f.x), "r"(f.y));
        }
    }

    // Epilogue: X0 -> fp16 scratch; rows >= garment -> fp32 output tail.
    const int r0 = row0 + arow;
    const int r1 = r0 + 8;
    #pragma unroll
    for (int nt = 0; nt < 16; nt++) {
        int col = nt * 8 + tq * 2;
        if (r0 < N) {
            *(half2*)&g_X0h[(size_t)r0 * D + col] = __floats2half2_rn(acc[nt][0], acc[nt][1]);
            if (r0 >= garment)
                *(float2*)&out[(size_t)(N + r0 - garment) * D + col] =
                    make_float2(acc[nt][0], acc[nt][1]);
        }
        if (r1 < N) {
            *(half2*)&g_X0h[(size_t)r1 * D + col] = __floats2half2_rn(acc[nt][2], acc[nt][3]);
            if (r1 >= garment)
                *(float2*)&out[(size_t)(N + r1 - garment) * D + col] =
                    make_float2(acc[nt][2], acc[nt][3]);
        }
    }
}

// ---------------------------------------------------------------------------
// Single-pass exclusive scan (decoupled lookback), 98 blocks x 1024
// ---------------------------------------------------------------------------
__global__ void scan_kernel() {
    __shared__ int wsum[32];
    __shared__ int s_total;
    __shared__ int s_prefix;
    const int t = threadIdx.x, lane = t & 31, warp = t >> 5;
    const int bid = blockIdx.x;
    const int i = bid * SCAN_B + t;
    int v = (i < NP) ? g_deg[i] : 0;

    int x = v;
    #pragma unroll
    for (int off = 1; off < 32; off <<= 1) {
        int y = __shfl_up_sync(0xffffffffu, x, off);
        if (lane >= off) x += y;
    }
    if (lane == 31) wsum[warp] = x;
    __syncthreads();
    if (warp == 0) {
        int s = wsum[lane];
        #pragma unroll
        for (int off = 1; off < 32; off <<= 1) {
            int y = __shfl_up_sync(0xffffffffu, s, off);
            if (lane >= off) s += y;
        }
        wsum[lane] = s;
    }
    __syncthreads();
    int incl = x + ((warp > 0) ? wsum[warp - 1] : 0);
    if (t == SCAN_B - 1) s_total = incl;
    __syncthreads();

    if (t == 0) {
        int total = s_total;
        if (bid == 0) {
            g_blk_inc[0] = total;
            __threadfence();
            atomicExch(&g_blk_flag[0], 2);
            s_prefix = 0;
        } else {
            g_blk_agg[bid] = total;
            __threadfence();
            atomicExch(&g_blk_flag[bid], 1);
            int pfx = 0;
            for (int j = bid - 1; j >= 0; j--) {
                int f;
                do { f = atomicAdd(&g_blk_flag[j], 0); } while (f == 0);
                if (f == 2) { pfx += atomicAdd(&g_blk_inc[j], 0); break; }
                pfx += atomicAdd(&g_blk_agg[j], 0);
            }
            s_prefix = pfx;
            g_blk_inc[bid] = pfx + total;
            __threadfence();
            atomicExch(&g_blk_flag[bid], 2);
        }
    }
    __syncthreads();
    if (i < NP) g_offs[i] = s_prefix + incl - v;
}

// ---------------------------------------------------------------------------
// Fill: 8 edges/thread (2x int4) for atomic MLP; one atomic + one STG.64 per
// edge (offs-shift trick; node kernel compensates).
// ---------------------------------------------------------------------------
__global__ void fill_kernel(const int* __restrict__ src,
                            const int* __restrict__ dst,
                            const float* __restrict__ ew, int E) {
    int base8 = (blockIdx.x * blockDim.x + threadIdx.x) * 2;   // in int4 units
    int E4 = E >> 2;
    #pragma unroll
    for (int q = 0; q < 2; q++) {
        int i4 = base8 + q;
        if (i4 >= E4) break;
        int4   s = ((const int4*)src)[i4];
        int4   d = ((const int4*)dst)[i4];
        float4 w = ((const float4*)ew)[i4];
        int idx;
        idx = atomicAdd(&g_offs[s.x], 1); g_csr[idx] = make_int2(d.x, __float_as_int(w.x));
        idx = atomicAdd(&g_offs[s.y], 1); g_csr[idx] = make_int2(d.y, __float_as_int(w.y));
        idx = atomicAdd(&g_offs[s.z], 1); g_csr[idx] = make_int2(d.z, __float_as_int(w.z));
        idx = atomicAdd(&g_offs[s.w], 1); g_csr[idx] = make_int2(d.w, __float_as_int(w.w));
    }
    if (base8 == 0) {
        for (int e = E4 << 2; e < E; e++) {
            int idx = atomicAdd(&g_offs[src[e]], 1);
            g_csr[idx] = make_int2(dst[e], __float_as_int(ew[e]));
        }
    }
}

// ---------------------------------------------------------------------------
// Node kernel: one warp per node, fp16 gather, fp32 accumulate, bias+ReLU.
// After fill, g_offs[i] = end of segment i (shifted).
// ---------------------------------------------------------------------------
__global__ void node_kernel(const float* __restrict__ b,
                            float* __restrict__ out, int N) {
    int node = (int)((blockIdx.x * (size_t)blockDim.x + threadIdx.x) >> 5);
    int lane = threadIdx.x & 31;
    if (node >= N) return;

    int beg = (node == 0) ? 0 : g_offs[node - 1];
    int end = g_offs[node];

    float4 acc = make_float4(0.f, 0.f, 0.f, 0.f);
    int i = beg;
    for (; i + 4 <= end; i += 4) {
        int2 p0 = g_csr[i],   p1 = g_csr[i+1];
        int2 p2 = g_csr[i+2], p3 = g_csr[i+3];
        float w0 = __int_as_float(p0.y), w1 = __int_as_float(p1.y);
        float w2 = __int_as_float(p2.y), w3 = __int_as_float(p3.y);
        uint2 u0 = ((const uint2*)(g_X0h + (size_t)p0.x * D))[lane];
        uint2 u1 = ((const uint2*)(g_X0h + (size_t)p1.x * D))[lane];
        uint2 u2 = ((const uint2*)(g_X0h + (size_t)p2.x * D))[lane];
        uint2 u3 = ((const uint2*)(g_X0h + (size_t)p3.x * D))[lane];
        float2 a, c;
        a = __half22float2(*(half2*)&u0.x); c = __half22float2(*(half2*)&u0.y);
        acc.x += w0*a.x; acc.y += w0*a.y; acc.z += w0*c.x; acc.w += w0*c.y;
        a = __half22float2(*(half2*)&u1.x); c = __half22float2(*(half2*)&u1.y);
        acc.x += w1*a.x; acc.y += w1*a.y; acc.z += w1*c.x; acc.w += w1*c.y;
        a = __half22float2(*(half2*)&u2.x); c = __half22float2(*(half2*)&u2.y);
        acc.x += w2*a.x; acc.y += w2*a.y; acc.z += w2*c.x; acc.w += w2*c.y;
        a = __half22float2(*(half2*)&u3.x); c = __half22float2(*(half2*)&u3.y);
        acc.x += w3*a.x; acc.y += w3*a.y; acc.z += w3*c.x; acc.w += w3*c.y;
    }
    for (; i < end; i++) {
        int2 p = g_csr[i];
        float wg = __int_as_float(p.y);
        uint2 u = ((const uint2*)(g_X0h + (size_t)p.x * D))[lane];
        float2 a = __half22float2(*(half2*)&u.x);
        float2 c = __half22float2(*(half2*)&u.y);
        acc.x += wg*a.x; acc.y += wg*a.y; acc.z += wg*c.x; acc.w += wg*c.y;
    }

    float4 bv = ((const float4*)b)[lane];
    acc.x = fmaxf(acc.x + bv.x, 0.f);
    acc.y = fmaxf(acc.y + bv.y, 0.f);
    acc.z = fmaxf(acc.z + bv.z, 0.f);
    acc.w = fmaxf(acc.w + bv.w, 0.f);
    ((float4*)(out + (size_t)node * D))[lane] = acc;
}

extern "C" void kernel_launch(void* const* d_in, const int* in_sizes, int n_in,
                              void* d_out, int out_size) {
    const float* notes = (const float*)d_in[0];
    const float* w     = (const float*)d_in[1];
    const float* b     = (const float*)d_in[2];
    const int*   esrc  = (const int*)d_in[3];
    const int*   edst  = (const int*)d_in[4];
    const float* ew    = (const float*)d_in[5];
    float*       out   = (float*)d_out;

    const int N = in_sizes[0] / D;          // 100000
    const int E = in_sizes[3];              // 1600000
    const int out_rows = out_size / D;      // 120000
    const int garment  = 2 * N - out_rows;  // 80000

    // w fragments + zero deg/scan state
    prep_kernel<<<16 + (NP + 255) / 256, 256>>>(w);

    // Fused tensor-core GEMM (128-row tiles, cp.async) + degree count
    const int smem_bytes = 4096 * 16 + 128 * SN_PITCH * 4;   // 133,120 B
    cudaFuncSetAttribute(gemm_count_kernel,
                         cudaFuncAttributeMaxDynamicSharedMemorySize, smem_bytes);
    gemm_count_kernel<<<GEMM_BLOCKS + CNT_BLOCKS, 256, smem_bytes>>>(
        notes, esrc, out, N, garment, E);

    // Offsets (single pass)
    scan_kernel<<<NBLK, SCAN_B>>>();

    // CSR fill
    fill_kernel<<<((E >> 3) + 255) / 256, 256>>>(esrc, edst, ew, E);

    // Gather-only aggregation, fp16 messages, fused bias + ReLU
    node_kernel<<<(N + 7) / 8, 256>>>(b, out, N);
}

// round 7
// speedup vs baseline: 1.1062x; 1.1062x over previous
#include <cuda_runtime.h>
#include <cuda_fp16.h>

#define D      128
#define NMAX   100000
#define NP     (NMAX + 1)
#define EMAX   1600000
#define SCAN_B 1024
#define NBLK   ((NP + SCAN_B - 1) / SCAN_B)   // 98

#define GEMM_BLOCKS ((NMAX + 63) / 64)        // 1563 (64-row tiles, 2 blk/SM)
#define CNT_BLOCKS  1184

// Scratch (device globals — no allocations allowed)
__device__ __half g_X0h[(size_t)NMAX * D];    // notes @ w in fp16 (25.6 MB)
__device__ uint4  g_wfrag[8 * 16 * 32];       // B fragments: {bh0,bh1,bl0,bl1}
__device__ int    g_offs[NP];
__device__ int2   g_csr[EMAX];                // packed {dst, w_bits}

// Zeroed once per launch by a single cudaMemsetAsync graph node
struct ScanScratch {
    int deg[NP];
    int flag[NBLK];    // 0 none, 1 aggregate, 2 inclusive
    int agg[NBLK];
    int inc[NBLK];
};
__device__ ScanScratch g_ss;

static __device__ __forceinline__ unsigned pack_bf16x2(float f0, float f1) {
    unsigned h;
    asm("cvt.rn.bf16x2.f32 %0, %1, %2;" : "=r"(h) : "f"(f1), "f"(f0));
    return h;
}

// ---------------------------------------------------------------------------
// Prep + count: blocks [0,16) build w fragments in mma register order;
// remaining blocks do the int4-vectorized degree histogram (g_ss.deg is
// pre-zeroed by the memset node).
// ---------------------------------------------------------------------------
__global__ void prep_count_kernel(const float* __restrict__ w,
                                  const int* __restrict__ esrc, int E) {
    if (blockIdx.x < 16) {
        int f = blockIdx.x * 256 + threadIdx.x;   // 0..4095
        int lane = f & 31;
        int nt   = (f >> 5) & 15;
        int ks   = f >> 9;
        int g  = lane >> 2;
        int tq = lane & 3;
        int n  = nt * 8 + g;
        int k0 = ks * 16 + 2 * tq;
        int k1 = k0 + 8;

        float a0 = w[(k0)     * D + n];
        float a1 = w[(k0 + 1) * D + n];
        float c0 = w[(k1)     * D + n];
        float c1 = w[(k1 + 1) * D + n];

        unsigned bh0 = pack_bf16x2(a0, a1);
        unsigned bh1 = pack_bf16x2(c0, c1);
        float h0 = __uint_as_float(bh0 << 16);
        float h1 = __uint_as_float(bh0 & 0xffff0000u);
        float h2 = __uint_as_float(bh1 << 16);
        float h3 = __uint_as_float(bh1 & 0xffff0000u);
        unsigned bl0 = pack_bf16x2(a0 - h0, a1 - h1);
        unsigned bl1 = pack_bf16x2(c0 - h2, c1 - h3);

        g_wfrag[f] = make_uint4(bh0, bh1, bl0, bl1);
    } else {
        int cb   = blockIdx.x - 16;
        int tidg = cb * 256 + threadIdx.x;
        int nth  = CNT_BLOCKS * 256;
        int E4   = E >> 2;
        const int4* s4 = (const int4*)esrc;
        for (int i = tidg; i < E4; i += nth) {
            int4 s = s4[i];
            atomicAdd(&g_ss.deg[s.x], 1);
            atomicAdd(&g_ss.deg[s.y], 1);
            atomicAdd(&g_ss.deg[s.z], 1);
            atomicAdd(&g_ss.deg[s.w], 1);
        }
        if (tidg == 0)
            for (int e = E4 << 2; e < E; e++) atomicAdd(&g_ss.deg[esrc[e]], 1);
    }
}

// ---------------------------------------------------------------------------
// Tensor-core GEMM (bf16 3-term compensated): 64 rows x 128 cols, 4 warps,
// 99 KB smem -> 2 blocks/SM (staging of one block hides under the other's
// MMA work). X0 -> fp16 scratch; rows >= garment -> fp32 output tail.
// ---------------------------------------------------------------------------
#define SN_PITCH 132

__global__ void __launch_bounds__(128) gemm_kernel(
        const float* __restrict__ notes,
        float* __restrict__ out, int N, int garment) {
    extern __shared__ char smem_raw[];
    float* s_n  = (float*)smem_raw;                           // [64][132] f32
    uint4* s_bf = (uint4*)(smem_raw + 64 * SN_PITCH * 4);     // [8*16*32]

    const int t    = threadIdx.x;
    const int warp = t >> 5;
    const int lane = t & 31;
    const int g    = lane >> 2;
    const int tq   = lane & 3;
    const int row0 = blockIdx.x * 64;

    #pragma unroll
    for (int i = t; i < 4096; i += 128) s_bf[i] = g_wfrag[i];

    const float4* n4 = (const float4*)notes;
    #pragma unroll
    for (int i = t; i < 2048; i += 128) {
        int r = i >> 5, c4 = i & 31;
        int gr = row0 + r;
        float4 v = make_float4(0.f, 0.f, 0.f, 0.f);
        if (gr < N) v = n4[(size_t)gr * 32 + c4];
        *(float4*)&s_n[r * SN_PITCH + c4 * 4] = v;
    }
    __syncthreads();

    float acc[16][4];
    #pragma unroll
    for (int nt = 0; nt < 16; nt++)
        #pragma unroll
        for (int j = 0; j < 4; j++) acc[nt][j] = 0.f;

    const int arow = warp * 16 + g;

    #pragma unroll
    for (int ks = 0; ks < 8; ks++) {
        unsigned ahi[4], alo[4];
        #pragma unroll
        for (int i = 0; i < 4; i++) {
            int r = arow + (i & 1) * 8;
            int k = ks * 16 + tq * 2 + (i >> 1) * 8;
            float2 f = *(const float2*)&s_n[r * SN_PITCH + k];
            unsigned h = pack_bf16x2(f.x, f.y);
            float hx = __uint_as_float(h << 16);
            float hy = __uint_as_float(h & 0xffff0000u);
            ahi[i] = h;
            alo[i] = pack_bf16x2(f.x - hx, f.y - hy);
        }
        const uint4* bf = &s_bf[ks * 16 * 32 + lane];
        #pragma unroll
        for (int nt = 0; nt < 16; nt++) {
            uint4 f = bf[nt * 32];
            asm volatile(
                "mma.sync.aligned.m16n8k16.row.col.f32.bf16.bf16.f32 "
                "{%0,%1,%2,%3}, {%4,%5,%6,%7}, {%8,%9}, {%0,%1,%2,%3};"
                : "+f"(acc[nt][0]), "+f"(acc[nt][1]), "+f"(acc[nt][2]), "+f"(acc[nt][3])
                : "r"(ahi[0]), "r"(ahi[1]), "r"(ahi[2]), "r"(ahi[3]),
                  "r"(f.x), "r"(f.y));
            asm volatile(
                "mma.sync.aligned.m16n8k16.row.col.f32.bf16.bf16.f32 "
                "{%0,%1,%2,%3}, {%4,%5,%6,%7}, {%8,%9}, {%0,%1,%2,%3};"
                : "+f"(acc[nt][0]), "+f"(acc[nt][1]), "+f"(acc[nt][2]), "+f"(acc[nt][3])
                : "r"(ahi[0]), "r"(ahi[1]), "r"(ahi[2]), "r"(ahi[3]),
                  "r"(f.z), "r"(f.w));
            asm volatile(
                "mma.sync.aligned.m16n8k16.row.col.f32.bf16.bf16.f32 "
                "{%0,%1,%2,%3}, {%4,%5,%6,%7}, {%8,%9}, {%0,%1,%2,%3};"
                : "+f"(acc[nt][0]), "+f"(acc[nt][1]), "+f"(acc[nt][2]), "+f"(acc[nt][3])
                : "r"(alo[0]), "r"(alo[1]), "r"(alo[2]), "r"(alo[3]),
                  "r"(f.x), "r"(f.y));
        }
    }

    const int r0 = row0 + arow;
    const int r1 = r0 + 8;
    #pragma unroll
    for (int nt = 0; nt < 16; nt++) {
        int col = nt * 8 + tq * 2;
        if (r0 < N) {
            *(half2*)&g_X0h[(size_t)r0 * D + col] = __floats2half2_rn(acc[nt][0], acc[nt][1]);
            if (r0 >= garment)
                *(float2*)&out[(size_t)(N + r0 - garment) * D + col] =
                    make_float2(acc[nt][0], acc[nt][1]);
        }
        if (r1 < N) {
            *(half2*)&g_X0h[(size_t)r1 * D + col] = __floats2half2_rn(acc[nt][2], acc[nt][3]);
            if (r1 >= garment)
                *(float2*)&out[(size_t)(N + r1 - garment) * D + col] =
                    make_float2(acc[nt][2], acc[nt][3]);
        }
    }
}

// ---------------------------------------------------------------------------
// Single-pass exclusive scan (decoupled lookback), 98 blocks x 1024
// ---------------------------------------------------------------------------
__global__ void scan_kernel() {
    __shared__ int wsum[32];
    __shared__ int s_total;
    __shared__ int s_prefix;
    const int t = threadIdx.x, lane = t & 31, warp = t >> 5;
    const int bid = blockIdx.x;
    const int i = bid * SCAN_B + t;
    int v = (i < NP) ? g_ss.deg[i] : 0;

    int x = v;
    #pragma unroll
    for (int off = 1; off < 32; off <<= 1) {
        int y = __shfl_up_sync(0xffffffffu, x, off);
        if (lane >= off) x += y;
    }
    if (lane == 31) wsum[warp] = x;
    __syncthreads();
    if (warp == 0) {
        int s = wsum[lane];
        #pragma unroll
        for (int off = 1; off < 32; off <<= 1) {
            int y = __shfl_up_sync(0xffffffffu, s, off);
            if (lane >= off) s += y;
        }
        wsum[lane] = s;
    }
    __syncthreads();
    int incl = x + ((warp > 0) ? wsum[warp - 1] : 0);
    if (t == SCAN_B - 1) s_total = incl;
    __syncthreads();

    if (t == 0) {
        int total = s_total;
        if (bid == 0) {
            g_ss.inc[0] = total;
            __threadfence();
            atomicExch(&g_ss.flag[0], 2);
            s_prefix = 0;
        } else {
            g_ss.agg[bid] = total;
            __threadfence();
            atomicExch(&g_ss.flag[bid], 1);
            int pfx = 0;
            for (int j = bid - 1; j >= 0; j--) {
                int f;
                do { f = atomicAdd(&g_ss.flag[j], 0); } while (f == 0);
                if (f == 2) { pfx += atomicAdd(&g_ss.inc[j], 0); break; }
                pfx += atomicAdd(&g_ss.agg[j], 0);
            }
            s_prefix = pfx;
            g_ss.inc[bid] = pfx + total;
            __threadfence();
            atomicExch(&g_ss.flag[bid], 2);
        }
    }
    __syncthreads();
    if (i < NP) g_offs[i] = s_prefix + incl - v;
}

// ---------------------------------------------------------------------------
// Fill: 4 edges/thread; all 4 atomics issued before the 4 dependent stores
// (MLP against L2-atomic latency). One atomic + one STG.64 per edge
// (offs-shift trick; node kernel compensates).
// ---------------------------------------------------------------------------
__global__ void fill_kernel(const int* __restrict__ src,
                            const int* __restrict__ dst,
                            const float* __restrict__ ew, int E) {
    int i4 = blockIdx.x * blockDim.x + threadIdx.x;
    int E4 = E >> 2;
    if (i4 < E4) {
        int4   s = ((const int4*)src)[i4];
        int4   d = ((const int4*)dst)[i4];
        float4 w = ((const float4*)ew)[i4];
        int i0 = atomicAdd(&g_offs[s.x], 1);
        int i1 = atomicAdd(&g_offs[s.y], 1);
        int i2 = atomicAdd(&g_offs[s.z], 1);
        int i3 = atomicAdd(&g_offs[s.w], 1);
        g_csr[i0] = make_int2(d.x, __float_as_int(w.x));
        g_csr[i1] = make_int2(d.y, __float_as_int(w.y));
        g_csr[i2] = make_int2(d.z, __float_as_int(w.z));
        g_csr[i3] = make_int2(d.w, __float_as_int(w.w));
    }
    if (i4 == 0) {
        for (int e = E4 << 2; e < E; e++) {
            int idx = atomicAdd(&g_offs[src[e]], 1);
            g_csr[idx] = make_int2(dst[e], __float_as_int(ew[e]));
        }
    }
}

// ---------------------------------------------------------------------------
// Node kernel: one warp per node, fp16 gather, fp32 accumulate, bias+ReLU.
// After fill, g_offs[i] = end of segment i (shifted).
// ---------------------------------------------------------------------------
__global__ void node_kernel(const float* __restrict__ b,
                            float* __restrict__ out, int N) {
    int node = (int)((blockIdx.x * (size_t)blockDim.x + threadIdx.x) >> 5);
    int lane = threadIdx.x & 31;
    if (node >= N) return;

    int beg = (node == 0) ? 0 : g_offs[node - 1];
    int end = g_offs[node];

    float4 acc = make_float4(0.f, 0.f, 0.f, 0.f);
    int i = beg;
    for (; i + 4 <= end; i += 4) {
        int2 p0 = g_csr[i],   p1 = g_csr[i+1];
        int2 p2 = g_csr[i+2], p3 = g_csr[i+3];
        float w0 = __int_as_float(p0.y), w1 = __int_as_float(p1.y);
        float w2 = __int_as_float(p2.y), w3 = __int_as_float(p3.y);
        uint2 u0 = ((const uint2*)(g_X0h + (size_t)p0.x * D))[lane];
        uint2 u1 = ((const uint2*)(g_X0h + (size_t)p1.x * D))[lane];
        uint2 u2 = ((const uint2*)(g_X0h + (size_t)p2.x * D))[lane];
        uint2 u3 = ((const uint2*)(g_X0h + (size_t)p3.x * D))[lane];
        float2 a, c;
        a = __half22float2(*(half2*)&u0.x); c = __half22float2(*(half2*)&u0.y);
        acc.x += w0*a.x; acc.y += w0*a.y; acc.z += w0*c.x; acc.w += w0*c.y;
        a = __half22float2(*(half2*)&u1.x); c = __half22float2(*(half2*)&u1.y);
        acc.x += w1*a.x; acc.y += w1*a.y; acc.z += w1*c.x; acc.w += w1*c.y;
        a = __half22float2(*(half2*)&u2.x); c = __half22float2(*(half2*)&u2.y);
        acc.x += w2*a.x; acc.y += w2*a.y; acc.z += w2*c.x; acc.w += w2*c.y;
        a = __half22float2(*(half2*)&u3.x); c = __half22float2(*(half2*)&u3.y);
        acc.x += w3*a.x; acc.y += w3*a.y; acc.z += w3*c.x; acc.w += w3*c.y;
    }
    for (; i < end; i++) {
        int2 p = g_csr[i];
        float wg = __int_as_float(p.y);
        uint2 u = ((const uint2*)(g_X0h + (size_t)p.x * D))[lane];
        float2 a = __half22float2(*(half2*)&u.x);
        float2 c = __half22float2(*(half2*)&u.y);
        acc.x += wg*a.x; acc.y += wg*a.y; acc.z += wg*c.x; acc.w += wg*c.y;
    }

    float4 bv = ((const float4*)b)[lane];
    acc.x = fmaxf(acc.x + bv.x, 0.f);
    acc.y = fmaxf(acc.y + bv.y, 0.f);
    acc.z = fmaxf(acc.z + bv.z, 0.f);
    acc.w = fmaxf(acc.w + bv.w, 0.f);
    ((float4*)(out + (size_t)node * D))[lane] = acc;
}

extern "C" void kernel_launch(void* const* d_in, const int* in_sizes, int n_in,
                              void* d_out, int out_size) {
    const float* notes = (const float*)d_in[0];
    const float* w     = (const float*)d_in[1];
    const float* b     = (const float*)d_in[2];
    const int*   esrc  = (const int*)d_in[3];
    const int*   edst  = (const int*)d_in[4];
    const float* ew    = (const float*)d_in[5];
    float*       out   = (float*)d_out;

    const int N = in_sizes[0] / D;          // 100000
    const int E = in_sizes[3];              // 1600000
    const int out_rows = out_size / D;      // 120000
    const int garment  = 2 * N - out_rows;  // 80000

    // One-time host objects (no device memory involved)
    static cudaStream_t s2 = nullptr;
    static cudaEvent_t ev_fork = nullptr, ev_join = nullptr;
    static void* ss_ptr = nullptr;
    if (!s2) {
        cudaStreamCreateWithFlags(&s2, cudaStreamNonBlocking);
        cudaEventCreateWithFlags(&ev_fork, cudaEventDisableTiming);
        cudaEventCreateWithFlags(&ev_join, cudaEventDisableTiming);
        cudaGetSymbolAddress(&ss_ptr, g_ss);
    }

    // Zero scan scratch (single memset graph node)
    cudaMemsetAsync(ss_ptr, 0, sizeof(ScanScratch), 0);

    // Prep (w fragments) + degree count in one launch
    prep_count_kernel<<<16 + CNT_BLOCKS, 256>>>(w, esrc, E);

    // Fork: scan+fill on side stream, GEMM on capture stream (concurrent)
    cudaEventRecord(ev_fork, 0);
    cudaStreamWaitEvent(s2, ev_fork, 0);

    scan_kernel<<<NBLK, SCAN_B, 0, s2>>>();
    fill_kernel<<<((E >> 2) + 255) / 256, 256, 0, s2>>>(esrc, edst, ew, E);
    cudaEventRecord(ev_join, s2);

    const int smem_bytes = 64 * SN_PITCH * 4 + 4096 * 16;   // 99,328 B
    cudaFuncSetAttribute(gemm_kernel,
                         cudaFuncAttributeMaxDynamicSharedMemorySize, smem_bytes);
    gemm_kernel<<<GEMM_BLOCKS, 128, smem_bytes>>>(notes, out, N, garment);

    // Join, then gather-aggregate
    cudaStreamWaitEvent(0, ev_join, 0);
    node_kernel<<<(N + 7) / 8, 256>>>(b, out, N);
}